// round 9
// baseline (speedup 1.0000x reference)
#include <cuda_runtime.h>
#include <cstdint>
#include <cstddef>

#define IN_F   8192
#define OUT_F  8192
#define BATCH  32
#define KSPLIT 32
#define KCHUNK (IN_F / KSPLIT)     // 256
#define NIT    (KCHUNK / 32)       // 8 k32 steps per CTA
#define MTILE  128                 // rows per CTA (8 warps x 16 rows)
#define THREADS 256
#define NS32   (IN_F / 32)         // 256 global k32 steps

#define S0 0.0625f                 // 2^-4
#define S1 0.00048828125f          // 2^-11

// B planes in s8 fragment order. uint2 index: (s*8 + j)*32 + g*4 + t
//   .x = s8x4 X[n][32s+4t .. +3], .y = s8x4 X[n][32s+16+4t .. +3]
//   n = 8j + g; n<32: plane q0, n>=32: plane q1. Total 512 KB.
__device__ uint32_t g_xbq[(size_t)NS32 * 256 * 2];
__device__ float g_partial[(size_t)KSPLIT * OUT_F * BATCH];      // 32 MB

// ---- helpers -----------------------------------------------------------------
__device__ __forceinline__ uint32_t prmt(uint32_t a, uint32_t b, uint32_t sel) {
    uint32_t d;
    asm("prmt.b32 %0, %1, %2, %3;" : "=r"(d) : "r"(a), "r"(b), "r"(sel));
    return d;
}
// 4 ternary int32 -> one s8x4 (byte0 of each; -1 -> 0xFF == s8 -1)
__device__ __forceinline__ uint32_t pack_s8(int4 w) {
    uint32_t lo = prmt((uint32_t)w.x, (uint32_t)w.y, 0x0040);
    uint32_t hi = prmt((uint32_t)w.z, (uint32_t)w.w, 0x0040);
    return prmt(lo, hi, 0x5410);
}
__device__ __forceinline__ void imma16832(int* d, uint32_t a0, uint32_t a1,
                                          uint32_t a2, uint32_t a3,
                                          uint32_t b0, uint32_t b1) {
    asm volatile(
        "mma.sync.aligned.m16n8k32.row.col.s32.s8.s8.s32 "
        "{%0,%1,%2,%3}, {%4,%5,%6,%7}, {%8,%9}, {%0,%1,%2,%3};"
        : "+r"(d[0]), "+r"(d[1]), "+r"(d[2]), "+r"(d[3])
        : "r"(a0), "r"(a1), "r"(a2), "r"(a3), "r"(b0), "r"(b1));
}
__device__ __forceinline__ int q8(float v, float mul, float lim) {
    float q = rintf(v * mul);
    q = fminf(fmaxf(q, -lim), lim);
    return (int)q;
}

// ---- Kernel 1: x[32][8192] f32 -> two s8 planes in fragment order ------------
// Thread handles 4 consecutive k: exactly one u32 slot per plane.
__global__ void xprep_kernel(const float* __restrict__ x) {
    int gidx = blockIdx.x * blockDim.x + threadIdx.x;   // 65536 threads
    int b  = gidx >> 11;
    int k4 = gidx & 2047;
    int k0 = k4 * 4;
    float4 v = ((const float4*)(x + (size_t)b * IN_F))[k4];

    int q0[4], q1[4];
    float xs[4] = {v.x, v.y, v.z, v.w};
#pragma unroll
    for (int i = 0; i < 4; i++) {
        q0[i] = q8(xs[i], 16.0f, 127.0f);               // plane0: x/S0
        float r = xs[i] - (float)q0[i] * S0;
        q1[i] = q8(r, 2048.0f, 127.0f);                 // plane1: r/S1
    }
    uint32_t p0 = (uint32_t)(q0[0] & 0xFF) | ((uint32_t)(q0[1] & 0xFF) << 8) |
                  ((uint32_t)(q0[2] & 0xFF) << 16) | ((uint32_t)(q0[3] & 0xFF) << 24);
    uint32_t p1 = (uint32_t)(q1[0] & 0xFF) | ((uint32_t)(q1[1] & 0xFF) << 8) |
                  ((uint32_t)(q1[2] & 0xFF) << 16) | ((uint32_t)(q1[3] & 0xFF) << 24);

    int s = k0 >> 5;
    int q = k0 & 31;
    int t = (q & 15) >> 2;
    int h = q >> 4;                                     // 0 -> .x, 1 -> .y

    // plane0: n = b; plane1: n = b + 32
    int j0 = b >> 3, g0 = b & 7;
    size_t i0 = ((size_t)(s * 8 + j0)      * 32 + g0 * 4 + t) * 2 + h;
    size_t i1 = ((size_t)(s * 8 + j0 + 4)  * 32 + g0 * 4 + t) * 2 + h;
    g_xbq[i0] = p0;
    g_xbq[i1] = p1;
}

// ---- Kernel 2: s8 IMMA GEMM, B staged in smem --------------------------------
// grid=(OUT_F/MTILE, KSPLIT)=(64,32)=2048 CTAs. Warp owns 16 rows x N=64.
// A (weights, DRAM stream) prefetched one k32 step ahead as raw int4; packed
// to s8 via PRMT just before the MMA burst. B via conflict-free LDS.64.
__global__ void __launch_bounds__(THREADS, 2)
gemm_kernel(const int* __restrict__ W) {
    __shared__ uint2 sB[NIT * 256];                     // 16 KB

    const int tid  = threadIdx.x;
    const int lane = tid & 31;
    const int warp = tid >> 5;                          // 0..7
    const int g    = lane >> 2;                         // 0..7
    const int t    = lane & 3;                          // 0..3

    const int rowbase = blockIdx.x * MTILE + warp * 16;
    const int kbase   = blockIdx.y * KCHUNK;
    const int sbase   = kbase >> 5;

    // Stage this CTA's B slice (contiguous 16 KB of g_xbq), coalesced.
    {
        const uint4* __restrict__ src =
            (const uint4*)(((const uint2*)g_xbq) + (size_t)sbase * 256);
        uint4* dst = (uint4*)sB;
#pragma unroll
        for (int i = tid; i < NIT * 128; i += THREADS) dst[i] = src[i];
    }

    const int* __restrict__ pA = W + (size_t)(rowbase + g) * IN_F + kbase + 4 * t;

    int acc[8][4];
#pragma unroll
    for (int j = 0; j < 8; j++)
#pragma unroll
        for (int e = 0; e < 4; e++) acc[j][e] = 0;

    int4 ca[4], na[4];

#define LOAD_A(dst, ko)                                                \
    do {                                                               \
        dst[0] = *(const int4*)(pA + (ko));                            \
        dst[1] = *(const int4*)(pA + (size_t)8 * IN_F + (ko));         \
        dst[2] = *(const int4*)(pA + (ko) + 16);                       \
        dst[3] = *(const int4*)(pA + (size_t)8 * IN_F + (ko) + 16);    \
    } while (0)

    LOAD_A(ca, 0);
    __syncthreads();

#pragma unroll 2
    for (int it = 0; it < NIT; ++it) {
        if (it + 1 < NIT) LOAD_A(na, (it + 1) * 32);

        uint32_t A0 = pack_s8(ca[0]);
        uint32_t A1 = pack_s8(ca[1]);
        uint32_t A2 = pack_s8(ca[2]);
        uint32_t A3 = pack_s8(ca[3]);

        const uint2* __restrict__ bp = sB + it * 256 + g * 4 + t;
#pragma unroll
        for (int j = 0; j < 8; j++) {
            uint2 bv = bp[j * 32];                      // LDS.64, conflict-free
            imma16832(acc[j], A0, A1, A2, A3, bv.x, bv.y);
        }

#pragma unroll
        for (int q = 0; q < 4; q++) ca[q] = na[q];
    }

    // Epilogue: out = S0*plane0 (j<4) + S1*plane1 (j+4); store f32 partials.
    float* pk = g_partial + (size_t)blockIdx.y * OUT_F * BATCH;
    const int r0 = rowbase + g;
#pragma unroll
    for (int j = 0; j < 4; j++) {
        const int n0 = 8 * j + 2 * t;
        float2 v0, v1;
        v0.x = S0 * (float)acc[j][0] + S1 * (float)acc[j + 4][0];
        v0.y = S0 * (float)acc[j][1] + S1 * (float)acc[j + 4][1];
        v1.x = S0 * (float)acc[j][2] + S1 * (float)acc[j + 4][2];
        v1.y = S0 * (float)acc[j][3] + S1 * (float)acc[j + 4][3];
        *(float2*)(pk + (size_t)r0 * BATCH + n0)       = v0;
        *(float2*)(pk + (size_t)(r0 + 8) * BATCH + n0) = v1;
    }
}

// ---- Kernel 3: reduce k-splits, apply softplus scale + bias -----------------
__global__ void reduce_kernel(const float* __restrict__ log_scale,
                              const float* __restrict__ bias,
                              float* __restrict__ out) {
    int g  = blockIdx.x * blockDim.x + threadIdx.x;
    int o  = g >> 3;
    int bq = g & 7;

    const float4* __restrict__ base = (const float4*)g_partial;
    float4 s = make_float4(0.f, 0.f, 0.f, 0.f);
#pragma unroll
    for (int ky = 0; ky < KSPLIT; ky++) {
        float4 p = base[((size_t)ky * OUT_F + o) * (BATCH / 4) + bq];
        s.x += p.x; s.y += p.y; s.z += p.z; s.w += p.w;
    }

    float ls = log_scale[o];
    float sp = (ls > 20.0f) ? ls : log1pf(expf(ls));
    float sc = fmaxf(sp, 1e-4f);
    float bi = bias[o];

    int b0 = bq << 2;
    out[(size_t)(b0 + 0) * OUT_F + o] = fmaf(sc, s.x, bi);
    out[(size_t)(b0 + 1) * OUT_F + o] = fmaf(sc, s.y, bi);
    out[(size_t)(b0 + 2) * OUT_F + o] = fmaf(sc, s.z, bi);
    out[(size_t)(b0 + 3) * OUT_F + o] = fmaf(sc, s.w, bi);
}

// ---- Launch ------------------------------------------------------------------
extern "C" void kernel_launch(void* const* d_in, const int* in_sizes, int n_in,
                              void* d_out, int out_size) {
    const float* x  = nullptr;
    const int*   W  = nullptr;
    const float* ls = nullptr;
    const float* bi = nullptr;
    for (int i = 0; i < n_in; i++) {
        long long sz = in_sizes[i];
        if (sz == (long long)OUT_F * IN_F)      W = (const int*)d_in[i];
        else if (sz == (long long)BATCH * IN_F) x = (const float*)d_in[i];
        else if (sz == OUT_F) {
            if (!ls) ls = (const float*)d_in[i];
            else     bi = (const float*)d_in[i];
        }
    }
    float* out = (float*)d_out;

    xprep_kernel<<<(BATCH * IN_F / 4) / 128, 128>>>(x);

    dim3 grid(OUT_F / MTILE, KSPLIT);            // (64, 32) = 2048 CTAs
    gemm_kernel<<<grid, THREADS>>>(W);

    reduce_kernel<<<(OUT_F * BATCH / 4) / 256, 256>>>(ls, bi, out);
}

// round 10
// speedup vs baseline: 1.0761x; 1.0761x over previous
#include <cuda_runtime.h>
#include <cstdint>
#include <cstddef>

#define IN_F   8192
#define OUT_F  8192
#define BATCH  32
#define KSPLIT 16
#define KCHUNK (IN_F / KSPLIT)     // 512
#define NIT    (KCHUNK / 32)       // 16 k32 steps per CTA
#define MTILE  128                 // rows per CTA (8 warps x 16 rows)
#define THREADS 256
#define NS32   (IN_F / 32)         // 256 global k32 steps

#define S0 0.0625f                 // 2^-4
#define S1 0.00048828125f          // 2^-11

// B planes in s8 fragment order. uint2 index: (s*8 + j)*32 + g*4 + t
//   .x = s8x4 X[n][32s+4t .. +3], .y = s8x4 X[n][32s+16+4t .. +3]
//   n = 8j + g; n<32: plane q0, n>=32: plane q1. Total 512 KB.
__device__ uint32_t g_xbq[(size_t)NS32 * 256 * 2];
__device__ float g_partial[(size_t)KSPLIT * OUT_F * BATCH];      // 16 MB

// ---- helpers -----------------------------------------------------------------
__device__ __forceinline__ uint32_t prmt(uint32_t a, uint32_t b, uint32_t sel) {
    uint32_t d;
    asm("prmt.b32 %0, %1, %2, %3;" : "=r"(d) : "r"(a), "r"(b), "r"(sel));
    return d;
}
// 4 ternary int32 -> one s8x4 (byte0 of each; -1 -> 0xFF == s8 -1)
__device__ __forceinline__ uint32_t pack_s8(int4 w) {
    uint32_t lo = prmt((uint32_t)w.x, (uint32_t)w.y, 0x0040);
    uint32_t hi = prmt((uint32_t)w.z, (uint32_t)w.w, 0x0040);
    return prmt(lo, hi, 0x5410);
}
__device__ __forceinline__ void imma16832(int* d, uint32_t a0, uint32_t a1,
                                          uint32_t a2, uint32_t a3,
                                          uint32_t b0, uint32_t b1) {
    asm volatile(
        "mma.sync.aligned.m16n8k32.row.col.s32.s8.s8.s32 "
        "{%0,%1,%2,%3}, {%4,%5,%6,%7}, {%8,%9}, {%0,%1,%2,%3};"
        : "+r"(d[0]), "+r"(d[1]), "+r"(d[2]), "+r"(d[3])
        : "r"(a0), "r"(a1), "r"(a2), "r"(a3), "r"(b0), "r"(b1));
}
__device__ __forceinline__ int q8(float v, float mul, float lim) {
    float q = rintf(v * mul);
    q = fminf(fmaxf(q, -lim), lim);
    return (int)q;
}

// ---- Kernel 1: x[32][8192] f32 -> two s8 planes in fragment order ------------
__global__ void xprep_kernel(const float* __restrict__ x) {
    int gidx = blockIdx.x * blockDim.x + threadIdx.x;   // 65536 threads
    int b  = gidx >> 11;
    int k4 = gidx & 2047;
    int k0 = k4 * 4;
    float4 v = ((const float4*)(x + (size_t)b * IN_F))[k4];

    int q0[4], q1[4];
    float xs[4] = {v.x, v.y, v.z, v.w};
#pragma unroll
    for (int i = 0; i < 4; i++) {
        q0[i] = q8(xs[i], 16.0f, 127.0f);               // plane0: x/S0
        float r = xs[i] - (float)q0[i] * S0;
        q1[i] = q8(r, 2048.0f, 127.0f);                 // plane1: r/S1
    }
    uint32_t p0 = (uint32_t)(q0[0] & 0xFF) | ((uint32_t)(q0[1] & 0xFF) << 8) |
                  ((uint32_t)(q0[2] & 0xFF) << 16) | ((uint32_t)(q0[3] & 0xFF) << 24);
    uint32_t p1 = (uint32_t)(q1[0] & 0xFF) | ((uint32_t)(q1[1] & 0xFF) << 8) |
                  ((uint32_t)(q1[2] & 0xFF) << 16) | ((uint32_t)(q1[3] & 0xFF) << 24);

    int s = k0 >> 5;
    int q = k0 & 31;
    int t = (q & 15) >> 2;
    int h = q >> 4;                                     // 0 -> .x, 1 -> .y

    int j0 = b >> 3, g0 = b & 7;
    size_t i0 = ((size_t)(s * 8 + j0)     * 32 + g0 * 4 + t) * 2 + h;
    size_t i1 = ((size_t)(s * 8 + j0 + 4) * 32 + g0 * 4 + t) * 2 + h;
    g_xbq[i0] = p0;
    g_xbq[i1] = p1;
}

// ---- Kernel 2: s8 IMMA GEMM, 3-deep A prefetch, B in smem --------------------
// grid=(OUT_F/MTILE, KSPLIT)=(64,16)=1024 CTAs, occ 2 (16 warps/SM).
// 12 outstanding LDG.128 per warp keeps ~24 KB/SM in flight -> DRAM roofline.
__global__ void __launch_bounds__(THREADS, 2)
gemm_kernel(const int* __restrict__ W) {
    __shared__ uint2 sB[NIT * 256];                     // 32 KB

    const int tid  = threadIdx.x;
    const int lane = tid & 31;
    const int warp = tid >> 5;                          // 0..7
    const int g    = lane >> 2;                         // 0..7
    const int t    = lane & 3;                          // 0..3

    const int rowbase = blockIdx.x * MTILE + warp * 16;
    const int kbase   = blockIdx.y * KCHUNK;
    const int sbase   = kbase >> 5;

    // Stage this CTA's B slice (contiguous 32 KB of g_xbq), coalesced.
    {
        const uint4* __restrict__ src =
            (const uint4*)(((const uint2*)g_xbq) + (size_t)sbase * 256);
        uint4* dst = (uint4*)sB;
#pragma unroll
        for (int i = tid; i < NIT * 128; i += THREADS) dst[i] = src[i];
    }

    const int* __restrict__ pA = W + (size_t)(rowbase + g) * IN_F + kbase + 4 * t;

    int acc[8][4];
#pragma unroll
    for (int j = 0; j < 8; j++)
#pragma unroll
        for (int e = 0; e < 4; e++) acc[j][e] = 0;

    int4 buf[3][4];                                     // 3-deep circular prefetch

#define LOAD_A(dst, ko)                                                \
    do {                                                               \
        dst[0] = *(const int4*)(pA + (ko));                            \
        dst[1] = *(const int4*)(pA + (size_t)8 * IN_F + (ko));         \
        dst[2] = *(const int4*)(pA + (ko) + 16);                       \
        dst[3] = *(const int4*)(pA + (size_t)8 * IN_F + (ko) + 16);    \
    } while (0)

    LOAD_A(buf[0], 0);
    LOAD_A(buf[1], 32);
    LOAD_A(buf[2], 64);
    __syncthreads();

#pragma unroll
    for (int it = 0; it < NIT; ++it) {
        const int slot = it % 3;                        // static under full unroll
        uint32_t A0 = pack_s8(buf[slot][0]);
        uint32_t A1 = pack_s8(buf[slot][1]);
        uint32_t A2 = pack_s8(buf[slot][2]);
        uint32_t A3 = pack_s8(buf[slot][3]);

        if (it + 3 < NIT) LOAD_A(buf[slot], (it + 3) * 32);

        const uint2* __restrict__ bp = sB + it * 256 + g * 4 + t;
#pragma unroll
        for (int j = 0; j < 8; j++) {
            uint2 bv = bp[j * 32];                      // LDS.64, conflict-free
            imma16832(acc[j], A0, A1, A2, A3, bv.x, bv.y);
        }
    }

    // Epilogue: out = S0*plane0 (j<4) + S1*plane1 (j+4); store f32 partials.
    float* pk = g_partial + (size_t)blockIdx.y * OUT_F * BATCH;
    const int r0 = rowbase + g;
#pragma unroll
    for (int j = 0; j < 4; j++) {
        const int n0 = 8 * j + 2 * t;
        float2 v0, v1;
        v0.x = S0 * (float)acc[j][0] + S1 * (float)acc[j + 4][0];
        v0.y = S0 * (float)acc[j][1] + S1 * (float)acc[j + 4][1];
        v1.x = S0 * (float)acc[j][2] + S1 * (float)acc[j + 4][2];
        v1.y = S0 * (float)acc[j][3] + S1 * (float)acc[j + 4][3];
        *(float2*)(pk + (size_t)r0 * BATCH + n0)       = v0;
        *(float2*)(pk + (size_t)(r0 + 8) * BATCH + n0) = v1;
    }
}

// ---- Kernel 3: reduce k-splits, apply softplus scale + bias -----------------
__global__ void reduce_kernel(const float* __restrict__ log_scale,
                              const float* __restrict__ bias,
                              float* __restrict__ out) {
    int g  = blockIdx.x * blockDim.x + threadIdx.x;
    int o  = g >> 3;
    int bq = g & 7;

    const float4* __restrict__ base = (const float4*)g_partial;
    float4 s = make_float4(0.f, 0.f, 0.f, 0.f);
#pragma unroll
    for (int ky = 0; ky < KSPLIT; ky++) {
        float4 p = base[((size_t)ky * OUT_F + o) * (BATCH / 4) + bq];
        s.x += p.x; s.y += p.y; s.z += p.z; s.w += p.w;
    }

    float ls = log_scale[o];
    float sp = (ls > 20.0f) ? ls : log1pf(expf(ls));
    float sc = fmaxf(sp, 1e-4f);
    float bi = bias[o];

    int b0 = bq << 2;
    out[(size_t)(b0 + 0) * OUT_F + o] = fmaf(sc, s.x, bi);
    out[(size_t)(b0 + 1) * OUT_F + o] = fmaf(sc, s.y, bi);
    out[(size_t)(b0 + 2) * OUT_F + o] = fmaf(sc, s.z, bi);
    out[(size_t)(b0 + 3) * OUT_F + o] = fmaf(sc, s.w, bi);
}

// ---- Launch ------------------------------------------------------------------
extern "C" void kernel_launch(void* const* d_in, const int* in_sizes, int n_in,
                              void* d_out, int out_size) {
    const float* x  = nullptr;
    const int*   W  = nullptr;
    const float* ls = nullptr;
    const float* bi = nullptr;
    for (int i = 0; i < n_in; i++) {
        long long sz = in_sizes[i];
        if (sz == (long long)OUT_F * IN_F)      W = (const int*)d_in[i];
        else if (sz == (long long)BATCH * IN_F) x = (const float*)d_in[i];
        else if (sz == OUT_F) {
            if (!ls) ls = (const float*)d_in[i];
            else     bi = (const float*)d_in[i];
        }
    }
    float* out = (float*)d_out;

    xprep_kernel<<<(BATCH * IN_F / 4) / 128, 128>>>(x);

    dim3 grid(OUT_F / MTILE, KSPLIT);            // (64, 16) = 1024 CTAs
    gemm_kernel<<<grid, THREADS>>>(W);

    reduce_kernel<<<(OUT_F * BATCH / 4) / 256, 256>>>(ls, bi, out);
}